// round 7
// baseline (speedup 1.0000x reference)
#include <cuda_runtime.h>
#include <cuda_bf16.h>
#include <cstdint>

// scratch (device globals) — b=4, c=512, l=4096, all intermediates bf16
__device__ __nv_bfloat16 g_ht[4ull * 4096 * 512];   // H^T [b][l][c]
__device__ __nv_bfloat16 g_qkt[4ull * 4096 * 1024]; // [Q^T | K^T] [b][l][1024]
__device__ __nv_bfloat16 g_v [4ull * 512 * 4096];   // V   [b][c][l]
__device__ __nv_bfloat16 g_s [4ull * 4096 * 4096];  // P = exp(S*scale)
__device__ __nv_bfloat16 g_ot[4ull * 4096 * 512];   // O^T [b][l][c]
__device__ __nv_bfloat16 g_wqk[1024 * 512];         // [Wq; Wk]
__device__ __nv_bfloat16 g_wv[512 * 512], g_wp[512 * 512];
__device__ float g_bqk[1024];                        // [bq; bk]
__device__ float g_l[4 * 4096];                      // softmax row sums

// ---------------- helpers ----------------------------------------------------
__device__ __forceinline__ uint32_t smem_u32(const void* p) {
    uint32_t a;
    asm("{ .reg .u64 t; cvta.to.shared.u64 t, %1; cvt.u32.u64 %0, t; }"
        : "=r"(a) : "l"(p));
    return a;
}

__device__ __forceinline__ void ldsm4(uint32_t& r0, uint32_t& r1, uint32_t& r2,
                                      uint32_t& r3, uint32_t addr) {
    asm volatile("ldmatrix.sync.aligned.m8n8.x4.shared.b16 {%0,%1,%2,%3}, [%4];"
                 : "=r"(r0), "=r"(r1), "=r"(r2), "=r"(r3) : "r"(addr));
}

__device__ __forceinline__ void mma_bf16(float (&c)[4], const uint32_t (&a)[4],
                                         const uint32_t (&b)[2]) {
    asm volatile(
        "mma.sync.aligned.m16n8k16.row.col.f32.bf16.bf16.f32 "
        "{%0,%1,%2,%3},{%4,%5,%6,%7},{%8,%9},{%0,%1,%2,%3};"
        : "+f"(c[0]), "+f"(c[1]), "+f"(c[2]), "+f"(c[3])
        : "r"(a[0]), "r"(a[1]), "r"(a[2]), "r"(a[3]), "r"(b[0]), "r"(b[1]));
}

// FFMA-only exp: exp(x) = 2^i * 2^f. Degree-5 Taylor for 2^f, f in [0,1).
// No MUFU. rel err ~8e-5 over |x| <~ 30.
__device__ __forceinline__ float fexp(float x) {
    float t = fminf(fmaxf(x * 1.4426950408889634f, -125.0f), 125.0f);
    float fi = floorf(t);
    float f = t - fi;
    float p = 1.3333558146e-3f;
    p = p * f + 9.6181291076e-3f;
    p = p * f + 5.5504108664e-2f;
    p = p * f + 2.4022650696e-1f;
    p = p * f + 6.9314718056e-1f;
    p = p * f + 1.0f;
    return __int_as_float(__float_as_int(p) + ((int)fi << 23));
}

// smem: 3 stages x (A 128x(64+8) bf16 = 18432B, B same) = 110592B
#define ROW_B 144
#define A_BYTES 18432
#define STG_BYTES 36864
#define SMEM_TOTAL 110592

// stage: A 128x64 bf16 + B 128x64 bf16, K-major, cp.async 16B chunks
__device__ __forceinline__ void load_stage(
    uint32_t sbase, const __nv_bfloat16* __restrict__ Ab,
    const __nv_bfloat16* __restrict__ Bb, int64_t lda, int64_t ldb, int koff,
    int tid) {
#pragma unroll
    for (int rep = 0; rep < 8; rep++) {
        int u = tid + rep * 256;
        const __nv_bfloat16* g;
        uint32_t dst;
        if (u < 1024) {
            int row = u >> 3, c16 = u & 7;
            g = Ab + (int64_t)row * lda + koff + c16 * 8;
            dst = sbase + row * ROW_B + c16 * 16;
        } else {
            int vv = u - 1024;
            int row = vv >> 3, c16 = vv & 7;
            g = Bb + (int64_t)row * ldb + koff + c16 * 8;
            dst = sbase + A_BYTES + row * ROW_B + c16 * 16;
        }
        asm volatile("cp.async.cg.shared.global [%0], [%1], 16;"
                     :: "r"(dst), "l"(g) : "memory");
    }
}

// ---------------- generic bf16 tensor-core GEMM -------------------------------
// CTA tile 128(m) x 128(n), 8 warps, warp tile 64x32, BK=64 stages.
// D[m][n] = f( alpha * sum_k A[z][m][k] * B[z][n][k] )
// mode 0: + bias_m/bias_n (+resid if out_f32)
// mode 1: p = exp(v); store bf16; atomicAdd row sums (of rounded p) to lsum
// mode 2: v *= 1/lsum[row]
__global__ void __launch_bounds__(256, 2) mm_bf16(
    const __nv_bfloat16* __restrict__ A, int64_t lda, int64_t astr,
    const __nv_bfloat16* __restrict__ B, int64_t ldb, int64_t bstr,
    void* __restrict__ C, int64_t ldc, int64_t cstr, int K, float alpha,
    const float* __restrict__ bias_m, const float* __restrict__ bias_n,
    const float* __restrict__ resid, float* __restrict__ lsum,
    int mode, int out_f32)
{
    extern __shared__ char smem[];
    uint32_t sb = smem_u32(smem);
    int tid = threadIdx.x, lane = tid & 31, wid = tid >> 5;
    int wm = wid & 1, wn = wid >> 1;
    int m0 = blockIdx.y * 128, n0 = blockIdx.x * 128, z = blockIdx.z;
    const __nv_bfloat16* Ab = A + (int64_t)z * astr + (int64_t)m0 * lda;
    const __nv_bfloat16* Bb = B + (int64_t)z * bstr + (int64_t)n0 * ldb;

    const int S = K >> 6;      // BK = 64
    load_stage(sb, Ab, Bb, lda, ldb, 0, tid);
    asm volatile("cp.async.commit_group;" ::: "memory");
    if (S > 1) load_stage(sb + STG_BYTES, Ab, Bb, lda, ldb, 64, tid);
    asm volatile("cp.async.commit_group;" ::: "memory");

    float acc[4][4][4] = {};
    // ldsm lane addressing (byte offsets within a row)
    uint32_t a_row = wm * 64 + (lane & 15);
    uint32_t a_cs = ((lane >> 4) << 4);          // 0 or 16 bytes
    uint32_t b_row = wn * 32 + (lane & 7) + ((lane >> 4) << 3);
    uint32_t b_cs = (((lane >> 3) & 1) << 4);    // 0 or 16 bytes

    for (int s = 0; s < S; s++) {
        asm volatile("cp.async.wait_group 1;" ::: "memory");
        __syncthreads();
        if (s + 2 < S)
            load_stage(sb + ((s + 2) % 3) * STG_BYTES, Ab, Bb, lda, ldb,
                       (s + 2) * 64, tid);
        asm volatile("cp.async.commit_group;" ::: "memory");

        uint32_t sa = sb + (s % 3) * STG_BYTES;
        uint32_t sB = sa + A_BYTES;

        uint32_t afr[2][4][4];
        // prefetch A frags for kk=0
#pragma unroll
        for (int i = 0; i < 4; i++)
            ldsm4(afr[0][i][0], afr[0][i][1], afr[0][i][2], afr[0][i][3],
                  sa + (a_row + i * 16) * ROW_B + a_cs);
#pragma unroll
        for (int kk = 0; kk < 4; kk++) {
            int cur = kk & 1;
            if (kk < 3) {
                int nxt = cur ^ 1;
#pragma unroll
                for (int i = 0; i < 4; i++)
                    ldsm4(afr[nxt][i][0], afr[nxt][i][1], afr[nxt][i][2],
                          afr[nxt][i][3],
                          sa + (a_row + i * 16) * ROW_B + (kk + 1) * 32 + a_cs);
            }
            uint32_t b[4][2];
#pragma unroll
            for (int jt = 0; jt < 2; jt++) {
                uint32_t r0, r1, r2, r3;
                ldsm4(r0, r1, r2, r3,
                      sB + (b_row + jt * 16) * ROW_B + kk * 32 + b_cs);
                b[jt * 2][0] = r0; b[jt * 2][1] = r1;
                b[jt * 2 + 1][0] = r2; b[jt * 2 + 1][1] = r3;
            }
#pragma unroll
            for (int i = 0; i < 4; i++)
#pragma unroll
                for (int j = 0; j < 4; j++) mma_bf16(acc[i][j], afr[cur][i], b[j]);
        }
    }

    // ---------------- epilogue ----------------
#pragma unroll
    for (int i = 0; i < 4; i++) {
        int r0 = m0 + wm * 64 + i * 16 + (lane >> 2);
        float bm0 = bias_m ? bias_m[r0] : 0.0f;
        float bm1 = bias_m ? bias_m[r0 + 8] : 0.0f;
        float rl0 = 1.0f, rl1 = 1.0f;
        if (mode == 2) {
            rl0 = __fdividef(1.0f, lsum[z * 4096 + r0]);
            rl1 = __fdividef(1.0f, lsum[z * 4096 + r0 + 8]);
        }
        float rs0 = 0.0f, rs1 = 0.0f;
#pragma unroll
        for (int j = 0; j < 4; j++) {
            int cc = n0 + wn * 32 + j * 8 + (lane & 3) * 2;
            float v00 = acc[i][j][0] * alpha + bm0;
            float v01 = acc[i][j][1] * alpha + bm0;
            float v10 = acc[i][j][2] * alpha + bm1;
            float v11 = acc[i][j][3] * alpha + bm1;
            if (bias_n) {
                float b0 = bias_n[cc], b1 = bias_n[cc + 1];
                v00 += b0; v01 += b1; v10 += b0; v11 += b1;
            }
            if (mode == 1) {
                v00 = fexp(v00); v01 = fexp(v01);
                v10 = fexp(v10); v11 = fexp(v11);
            } else if (mode == 2) {
                v00 *= rl0; v01 *= rl0; v10 *= rl1; v11 *= rl1;
            }
            int64_t i0 = (int64_t)z * cstr + (int64_t)r0 * ldc + cc;
            int64_t i1 = i0 + 8 * ldc;
            if (out_f32) {
                float* Cf = (float*)C;
                if (resid) {
                    float2 t0 = *(const float2*)(resid + i0);
                    float2 t1 = *(const float2*)(resid + i1);
                    v00 += t0.x; v01 += t0.y; v10 += t1.x; v11 += t1.y;
                }
                *(float2*)(Cf + i0) = make_float2(v00, v01);
                *(float2*)(Cf + i1) = make_float2(v10, v11);
            } else {
                __nv_bfloat16* Cb = (__nv_bfloat16*)C;
                __nv_bfloat162 h0 = __float22bfloat162_rn(make_float2(v00, v01));
                __nv_bfloat162 h1 = __float22bfloat162_rn(make_float2(v10, v11));
                if (mode == 1) {
                    float2 q0 = __bfloat1622float2(h0);
                    float2 q1 = __bfloat1622float2(h1);
                    rs0 += q0.x + q0.y;
                    rs1 += q1.x + q1.y;
                }
                *(__nv_bfloat162*)(Cb + i0) = h0;
                *(__nv_bfloat162*)(Cb + i1) = h1;
            }
        }
        if (mode == 1) {
            rs0 += __shfl_xor_sync(0xffffffffu, rs0, 1);
            rs0 += __shfl_xor_sync(0xffffffffu, rs0, 2);
            rs1 += __shfl_xor_sync(0xffffffffu, rs1, 1);
            rs1 += __shfl_xor_sync(0xffffffffu, rs1, 2);
            if ((lane & 3) == 0) {
                atomicAdd(lsum + z * 4096 + r0, rs0);
                atomicAdd(lsum + z * 4096 + r0 + 8, rs1);
            }
        }
    }
}

// ---------------- zero the row-sum buffer -------------------------------------
__global__ void zero_l_kernel(float* __restrict__ l) {
    l[blockIdx.x * 1024 + threadIdx.x] = 0.0f;
}

// ---------------- weights fp32 -> bf16 (+ QK weight/bias concat) ---------------
// y=0: wq -> wqk[0:512], y=1: wk -> wqk[512:1024], y=2: wv, y=3: wp
__global__ void __launch_bounds__(256) cvt_w_kernel(
    const float* __restrict__ wq, const float* __restrict__ wk,
    const float* __restrict__ wv, const float* __restrict__ wp,
    const float* __restrict__ bq, const float* __restrict__ bk,
    __nv_bfloat16* __restrict__ owqk, __nv_bfloat16* __restrict__ owv,
    __nv_bfloat16* __restrict__ owp, float* __restrict__ obqk)
{
    const float* w = blockIdx.y == 0 ? wq : blockIdx.y == 1 ? wk
                     : blockIdx.y == 2 ? wv : wp;
    __nv_bfloat16* o = blockIdx.y == 0 ? owqk
                       : blockIdx.y == 1 ? owqk + 512 * 512
                       : blockIdx.y == 2 ? owv : owp;
    int i = (blockIdx.x * 256 + threadIdx.x) * 4;
    float4 t = *(const float4*)(w + i);
    *(__nv_bfloat162*)(o + i) = __float22bfloat162_rn(make_float2(t.x, t.y));
    *(__nv_bfloat162*)(o + i + 2) = __float22bfloat162_rn(make_float2(t.z, t.w));
    if (blockIdx.x == 0 && blockIdx.y == 0) {
        obqk[threadIdx.x] = bq[threadIdx.x];
        obqk[256 + threadIdx.x] = bq[256 + threadIdx.x];
        obqk[512 + threadIdx.x] = bk[threadIdx.x];
        obqk[768 + threadIdx.x] = bk[256 + threadIdx.x];
    }
}

// ---------------- GroupNorm -> transposed bf16 H^T [b][l][c] -------------------
__global__ void __launch_bounds__(256) groupnorm_t_kernel(
    const float* __restrict__ x, const float* __restrict__ scale,
    const float* __restrict__ bias, __nv_bfloat16* __restrict__ ht)
{
    __shared__ float tile[16 * 257];
    __shared__ float sh_s[8], sh_ss[8], s_stat[2];
    __shared__ float csc[16], cbi[16];

    int bi = blockIdx.x;           // b*32 + g
    int b = bi >> 5, g = bi & 31;
    const float* xg = x + (size_t)bi * 65536;

    float s = 0.f, ss = 0.f;
    const float4* xp = (const float4*)xg;
    for (int i = threadIdx.x; i < 16384; i += 256) {
        float4 t = xp[i];
        s  += t.x + t.y + t.z + t.w;
        ss += t.x * t.x + t.y * t.y + t.z * t.z + t.w * t.w;
    }
    int lane = threadIdx.x & 31, wrp = threadIdx.x >> 5;
#pragma unroll
    for (int o = 16; o; o >>= 1) {
        s  += __shfl_xor_sync(0xffffffffu, s, o);
        ss += __shfl_xor_sync(0xffffffffu, ss, o);
    }
    if (lane == 0) { sh_s[wrp] = s; sh_ss[wrp] = ss; }
    __syncthreads();
    if (threadIdx.x == 0) {
        float ts = 0.f, tss = 0.f;
        for (int i = 0; i < 8; i++) { ts += sh_s[i]; tss += sh_ss[i]; }
        float mean = ts / 65536.0f;
        float var  = tss / 65536.0f - mean * mean;
        s_stat[0] = mean;
        s_stat[1] = rsqrtf(var + 1e-6f);
    }
    __syncthreads();
    if (threadIdx.x < 16) {
        float sc = scale[g * 16 + threadIdx.x] * s_stat[1];
        csc[threadIdx.x] = sc;
        cbi[threadIdx.x] = bias[g * 16 + threadIdx.x] - s_stat[0] * sc;
    }
    __syncthreads();

    __nv_bfloat16* hb = ht + (size_t)b * 2097152 + g * 16;
    for (int l0 = 0; l0 < 4096; l0 += 256) {
#pragma unroll
        for (int c = 0; c < 16; c++)
            tile[c * 257 + threadIdx.x] =
                xg[c * 4096 + l0 + threadIdx.x] * csc[c] + cbi[c];
        __syncthreads();
#pragma unroll
        for (int rep = 0; rep < 16; rep++) {
            int idx = rep * 256 + threadIdx.x;
            int lp = idx >> 4, cc = idx & 15;
            hb[(size_t)(l0 + lp) * 512 + cc] =
                __float2bfloat16(tile[cc * 257 + lp]);
        }
        __syncthreads();
    }
}

// -----------------------------------------------------------------------------
extern "C" void kernel_launch(void* const* d_in, const int* in_sizes, int n_in,
                              void* d_out, int out_size)
{
    (void)in_sizes; (void)n_in; (void)out_size;
    const float* x  = (const float*)d_in[0];
    const float* gs = (const float*)d_in[1];
    const float* gb = (const float*)d_in[2];
    const float* wq = (const float*)d_in[3];
    const float* bq = (const float*)d_in[4];
    const float* wk = (const float*)d_in[5];
    const float* bk = (const float*)d_in[6];
    const float* wv = (const float*)d_in[7];
    const float* bv = (const float*)d_in[8];
    const float* wp = (const float*)d_in[9];
    const float* bp = (const float*)d_in[10];
    float* out = (float*)d_out;

    __nv_bfloat16 *ht, *qkt, *v, *s, *ot, *wqkb, *wvb, *wpb;
    float *l, *bqk;
    cudaGetSymbolAddress((void**)&ht, g_ht);
    cudaGetSymbolAddress((void**)&qkt, g_qkt);
    cudaGetSymbolAddress((void**)&v,  g_v);
    cudaGetSymbolAddress((void**)&s,  g_s);
    cudaGetSymbolAddress((void**)&ot, g_ot);
    cudaGetSymbolAddress((void**)&wqkb, g_wqk);
    cudaGetSymbolAddress((void**)&wvb, g_wv);
    cudaGetSymbolAddress((void**)&wpb, g_wp);
    cudaGetSymbolAddress((void**)&l,  g_l);
    cudaGetSymbolAddress((void**)&bqk, g_bqk);

    cudaFuncSetAttribute(mm_bf16, cudaFuncAttributeMaxDynamicSharedMemorySize,
                         SMEM_TOTAL);

    const float SCALE = 0.044194173824159216f;  // 512^-0.5
    const int64_t LC = 2097152, LS = 16777216, LQK = 4194304;

    cvt_w_kernel<<<dim3(256, 4), 256>>>(wq, wk, wv, wp, bq, bk,
                                        wqkb, wvb, wpb, bqk);
    groupnorm_t_kernel<<<128, 256>>>(x, gs, gb, ht);
    zero_l_kernel<<<16, 1024>>>(l);

    // [Q^T | K^T] [l][1024] : M=4096, N=1024, K=512
    mm_bf16<<<dim3(8, 32, 4), 256, SMEM_TOTAL>>>(ht, 512, LC, wqkb, 512, 0,
        qkt, 1024, LQK, 512, 1.0f, nullptr, bqk, nullptr, nullptr, 0, 0);
    // V[c][l] : M=512, N=4096, K=512
    mm_bf16<<<dim3(32, 4, 4), 256, SMEM_TOTAL>>>(wvb, 512, 0, ht, 512, LC,
        v, 4096, LC, 512, 1.0f, bv, nullptr, nullptr, nullptr, 0, 0);
    // P[i][j] = exp(scale * Q.K) : M=N=4096, K=512 (+ row sums into l)
    mm_bf16<<<dim3(32, 32, 4), 256, SMEM_TOTAL>>>(qkt, 1024, LQK,
        qkt + 512, 1024, LQK, s, 4096, LS, 512, SCALE,
        nullptr, nullptr, nullptr, l, 1, 0);
    // O^T[i][c] = (P @ V^T) / l[i] : M=4096, N=512, K=4096
    mm_bf16<<<dim3(4, 32, 4), 256, SMEM_TOTAL>>>(s, 4096, LS, v, 4096, LC,
        ot, 512, LC, 4096, 1.0f, nullptr, nullptr, nullptr, l, 2, 0);
    // out[c][l] = Wp @ O + bp + x : M=512, N=4096, K=512
    mm_bf16<<<dim3(32, 4, 4), 256, SMEM_TOTAL>>>(wpb, 512, 0, ot, 512, LC,
        out, 4096, LC, 512, 1.0f, bp, nullptr, x, nullptr, 0, 1);
}